// round 13
// baseline (speedup 1.0000x reference)
#include <cuda_runtime.h>
#include <cuda_bf16.h>
#include <math.h>

#define H 128
#define MAX_SRC 20000
#define MAX_DST 20000
#define MAX_E   640000

// ---------------- device scratch (no runtime allocation) ----------------
__device__ float g_h[MAX_SRC * H];
// A for readout GEMM, pre-split bf16 hi/lo: [row][512] (sum|max|mean|dst)
__device__ __align__(16) unsigned short g_agg_hi[MAX_DST * 512];
__device__ __align__(16) unsigned short g_agg_lo[MAX_DST * 512];
__device__ int   g_cnt[MAX_DST];          // zero-init at load; re-zeroed by scan_block
__device__ int   g_off[MAX_DST + 1];
__device__ int   g_cursor[MAX_DST];
__device__ int   g_perm[MAX_E];
__device__ int   g_bsum[32];
// W_readout transposed + bf16 hi/lo split: Wt[n][k]
__device__ __align__(16) unsigned short g_wt_hi[128 * 512];
__device__ __align__(16) unsigned short g_wt_lo[128 * 512];

// ---------------- small helpers ----------------
__device__ __forceinline__ unsigned int smem_u32(const void* p) {
    unsigned int a;
    asm("{ .reg .u64 t; cvta.to.shared.u64 t, %1; cvt.u32.u64 %0, t; }"
        : "=r"(a) : "l"(p));
    return a;
}
__device__ __forceinline__ unsigned short f2bf(float x) {
    __nv_bfloat16 h = __float2bfloat16_rn(x);
    return *reinterpret_cast<unsigned short*>(&h);
}
__device__ __forceinline__ float bf2f(unsigned short u) {
    __nv_bfloat16 h = *reinterpret_cast<__nv_bfloat16*>(&u);
    return __bfloat162float(h);
}
__device__ __forceinline__ void split_store(unsigned short* oh, unsigned short* ol,
                                            float4 v) {
    unsigned short h0 = f2bf(v.x), h1 = f2bf(v.y), h2 = f2bf(v.z), h3 = f2bf(v.w);
    unsigned short l0 = f2bf(v.x - bf2f(h0));
    unsigned short l1 = f2bf(v.y - bf2f(h1));
    unsigned short l2 = f2bf(v.z - bf2f(h2));
    unsigned short l3 = f2bf(v.w - bf2f(h3));
    uint2 uh = make_uint2((unsigned)h0 | ((unsigned)h1 << 16),
                          (unsigned)h2 | ((unsigned)h3 << 16));
    uint2 ul = make_uint2((unsigned)l0 | ((unsigned)l1 << 16),
                          (unsigned)l2 | ((unsigned)l3 << 16));
    *(uint2*)oh = uh;
    *(uint2*)ol = ul;
}

// ---------------- CSR build ----------------
__global__ void count_kernel(const int* __restrict__ edge_dst, int E) {
    int i = (blockIdx.x * blockDim.x + threadIdx.x) * 4;
    if (i + 3 < E) {
        int4 d = *(const int4*)(edge_dst + i);
        atomicAdd(&g_cnt[d.x], 1);
        atomicAdd(&g_cnt[d.y], 1);
        atomicAdd(&g_cnt[d.z], 1);
        atomicAdd(&g_cnt[d.w], 1);
    } else {
        for (int j = 0; j < 4 && i + j < E; j++)
            atomicAdd(&g_cnt[edge_dst[i + j]], 1);
    }
}

// block-local exclusive scan (warp-shuffle) + block totals.
// Also RE-ZEROES g_cnt after reading so the next graph replay starts clean
// (g_cnt is zero-initialized at module load for the first run).
__global__ void scan_block_kernel(int n) {
    __shared__ int warp_sums[32];
    int tid = threadIdx.x, lane = tid & 31, wid = tid >> 5;
    int i = blockIdx.x * 1024 + tid;
    int v = (i < n) ? g_cnt[i] : 0;
    if (i < n) g_cnt[i] = 0;
    int x = v;
#pragma unroll
    for (int d = 1; d < 32; d <<= 1) {
        int t = __shfl_up_sync(0xffffffffu, x, d);
        if (lane >= d) x += t;
    }
    if (lane == 31) warp_sums[wid] = x;
    __syncthreads();
    if (wid == 0) {
        int s = warp_sums[lane];
#pragma unroll
        for (int d = 1; d < 32; d <<= 1) {
            int t = __shfl_up_sync(0xffffffffu, s, d);
            if (lane >= d) s += t;
        }
        warp_sums[lane] = s;
    }
    __syncthreads();
    int warp_pre = (wid == 0) ? 0 : warp_sums[wid - 1];
    int incl = warp_pre + x;
    if (i < n) g_off[i] = incl - v;
    if (tid == 1023) g_bsum[blockIdx.x] = incl;
}

__global__ void scan_add_kernel(int nb, int n) {
    __shared__ int pre[33];
    int tid = threadIdx.x;
    if (tid < 32) {
        int v0 = (tid < nb) ? g_bsum[tid] : 0;
        int v = v0;
#pragma unroll
        for (int d = 1; d < 32; d <<= 1) {
            int t = __shfl_up_sync(0xffffffffu, v, d);
            if (tid >= d) v += t;
        }
        pre[tid] = v - v0;
        if (tid == 31) pre[32] = v;
    }
    __syncthreads();
    int i = blockIdx.x * 1024 + tid;
    if (i < n) {
        int o = g_off[i] + pre[blockIdx.x];
        g_off[i] = o;
        g_cursor[i] = o;
    }
    if (blockIdx.x == 0 && tid == 0) g_off[n] = pre[32];
}

__global__ void scatter_kernel(const int* __restrict__ edge_src,
                               const int* __restrict__ edge_dst, int E) {
    int i = (blockIdx.x * blockDim.x + threadIdx.x) * 4;
    if (i + 3 < E) {
        int4 d = *(const int4*)(edge_dst + i);
        int4 s = *(const int4*)(edge_src + i);
        g_perm[atomicAdd(&g_cursor[d.x], 1)] = s.x;
        g_perm[atomicAdd(&g_cursor[d.y], 1)] = s.y;
        g_perm[atomicAdd(&g_cursor[d.z], 1)] = s.z;
        g_perm[atomicAdd(&g_cursor[d.w], 1)] = s.w;
    } else {
        for (int j = 0; j < 4 && i + j < E; j++) {
            int d = edge_dst[i + j];
            int p = atomicAdd(&g_cursor[d], 1);
            g_perm[p] = edge_src[i + j];
        }
    }
}

// ---------------- W-transpose + bf16 hi/lo prep ----------------
__global__ void wt_prep_kernel(const float* __restrict__ Wr) {
    int idx = blockIdx.x * blockDim.x + threadIdx.x;
    if (idx >= 128 * 64) return;
    int n = idx >> 6;
    int k0 = (idx & 63) * 8;
    unsigned short hs[8], ls[8];
#pragma unroll
    for (int i = 0; i < 8; i++) {
        float x = Wr[(size_t)(k0 + i) * 128 + n];
        hs[i] = f2bf(x);
        ls[i] = f2bf(x - bf2f(hs[i]));
    }
    uint4 uh = make_uint4((unsigned)hs[0] | ((unsigned)hs[1] << 16),
                          (unsigned)hs[2] | ((unsigned)hs[3] << 16),
                          (unsigned)hs[4] | ((unsigned)hs[5] << 16),
                          (unsigned)hs[6] | ((unsigned)hs[7] << 16));
    uint4 ul = make_uint4((unsigned)ls[0] | ((unsigned)ls[1] << 16),
                          (unsigned)ls[2] | ((unsigned)ls[3] << 16),
                          (unsigned)ls[4] | ((unsigned)ls[5] << 16),
                          (unsigned)ls[6] | ((unsigned)ls[7] << 16));
    *(uint4*)(g_wt_hi + (size_t)n * 512 + k0) = uh;
    *(uint4*)(g_wt_lo + (size_t)n * 512 + k0) = ul;
}

// ---------------- aggregation over dst range [base, lim) ----------------
__global__ void agg_kernel(const float* __restrict__ dst_feat, int base, int lim) {
    int warp = base + ((blockIdx.x * blockDim.x + threadIdx.x) >> 5);
    int lane = threadIdx.x & 31;
    if (warp >= lim) return;
    int d = warp;
    int beg = g_off[d], end = g_off[d + 1];
    const float4* __restrict__ hv = (const float4*)g_h;

    float4 sum = make_float4(0.f, 0.f, 0.f, 0.f);
    float4 mx  = make_float4(-3.4e38f, -3.4e38f, -3.4e38f, -3.4e38f);

    int e = beg;
    for (; e + 7 < end; e += 8) {
        int s[8];
#pragma unroll
        for (int j = 0; j < 8; j++) s[j] = g_perm[e + j];
        float4 v[8];
#pragma unroll
        for (int j = 0; j < 8; j++) v[j] = hv[s[j] * 32 + lane];
#pragma unroll
        for (int j = 0; j < 8; j++) {
            sum.x += v[j].x; sum.y += v[j].y; sum.z += v[j].z; sum.w += v[j].w;
            mx.x = fmaxf(mx.x, v[j].x); mx.y = fmaxf(mx.y, v[j].y);
            mx.z = fmaxf(mx.z, v[j].z); mx.w = fmaxf(mx.w, v[j].w);
        }
    }
    for (; e < end; e++) {
        int s0 = g_perm[e];
        float4 v0 = hv[s0 * 32 + lane];
        sum.x += v0.x; sum.y += v0.y; sum.z += v0.z; sum.w += v0.w;
        mx.x = fmaxf(mx.x, v0.x); mx.y = fmaxf(mx.y, v0.y);
        mx.z = fmaxf(mx.z, v0.z); mx.w = fmaxf(mx.w, v0.w);
    }

    int cnt = end - beg;
    if (cnt == 0) mx = make_float4(0.f, 0.f, 0.f, 0.f);
    float inv = 1.0f / (float)(cnt > 0 ? cnt : 1);
    float4 mean = make_float4(sum.x * inv, sum.y * inv, sum.z * inv, sum.w * inv);
    float4 dv = ((const float4*)dst_feat)[d * 32 + lane];

    unsigned short* oh = g_agg_hi + (size_t)d * 512;
    unsigned short* ol = g_agg_lo + (size_t)d * 512;
    split_store(oh +   0 + lane * 4, ol +   0 + lane * 4, sum);
    split_store(oh + 128 + lane * 4, ol + 128 + lane * 4, mx);
    split_store(oh + 256 + lane * 4, ol + 256 + lane * 4, mean);
    split_store(oh + 384 + lane * 4, ol + 384 + lane * 4, dv);
}

// ---------------- tiling constants (FFMA MLP) ----------------
#define BM 144
#define BN 128
#define BK 16
#define NTHREADS 288
#define HS_PAD 136

// ---------------- fused MLP: h = src + lrelu(src@W1+b1)@W2 + b2 ----------------
__global__ __launch_bounds__(NTHREADS, 1) void mlp_fused_kernel(
    const float* __restrict__ src, const float* __restrict__ W1,
    const float* __restrict__ b1, const float* __restrict__ W2,
    const float* __restrict__ b2, int M)
{
    extern __shared__ float smem[];
    float* Ws = smem;                       // [2][BK][BN]
    float* As = smem + 4096;                // [2][BK][BM]
    float* Hs = smem + 4096 + 4608;         // [BM][HS_PAD]

    int tid = threadIdx.x;
    int block_row = blockIdx.x * BM;
    int tx = tid & 15, ty = tid >> 4;

    int a_row[2], a_col[2], w_k[2], w_n[2];
    bool w_ok[2];
#pragma unroll
    for (int l = 0; l < 2; l++) {
        int flat = tid + l * NTHREADS;
        a_row[l] = flat >> 2;
        a_col[l] = (flat & 3) * 4;
        w_ok[l] = flat < 512;
        int wf = w_ok[l] ? flat : 0;
        w_k[l] = wf >> 5;
        w_n[l] = (wf & 31) * 4;
    }

    float4 a_reg[2], w_reg[2];
    const int ntiles = H / BK;

    {
        auto fetch = [&](int t) {
#pragma unroll
            for (int l = 0; l < 2; l++) {
                int rg = block_row + a_row[l];
                a_reg[l] = (rg < M) ? *(const float4*)(src + (size_t)rg * H + t * BK + a_col[l])
                                    : make_float4(0.f, 0.f, 0.f, 0.f);
                if (w_ok[l])
                    w_reg[l] = *(const float4*)(W1 + (size_t)(t * BK + w_k[l]) * BN + w_n[l]);
            }
        };
        auto stage = [&](int buf) {
#pragma unroll
            for (int l = 0; l < 2; l++) {
                float* Ab = As + buf * (BK * BM);
                Ab[(a_col[l] + 0) * BM + a_row[l]] = a_reg[l].x;
                Ab[(a_col[l] + 1) * BM + a_row[l]] = a_reg[l].y;
                Ab[(a_col[l] + 2) * BM + a_row[l]] = a_reg[l].z;
                Ab[(a_col[l] + 3) * BM + a_row[l]] = a_reg[l].w;
                if (w_ok[l])
                    *(float4*)(Ws + buf * (BK * BN) + w_k[l] * BN + w_n[l]) = w_reg[l];
            }
        };

        float acc[8][8] = {};
        fetch(0); stage(0);
        __syncthreads();
        for (int t = 0; t < ntiles; t++) {
            if (t + 1 < ntiles) fetch(t + 1);
            const float* Ab = As + (t & 1) * (BK * BM);
            const float* Wb = Ws + (t & 1) * (BK * BN);
#pragma unroll
            for (int k = 0; k < BK; k++) {
                float4 a0 = *(const float4*)(Ab + k * BM + ty * 8);
                float4 a1 = *(const float4*)(Ab + k * BM + ty * 8 + 4);
                float4 c0 = *(const float4*)(Wb + k * BN + tx * 8);
                float4 c1 = *(const float4*)(Wb + k * BN + tx * 8 + 4);
                float av[8] = {a0.x, a0.y, a0.z, a0.w, a1.x, a1.y, a1.z, a1.w};
                float bv[8] = {c0.x, c0.y, c0.z, c0.w, c1.x, c1.y, c1.z, c1.w};
#pragma unroll
                for (int i = 0; i < 8; i++)
#pragma unroll
                    for (int j = 0; j < 8; j++)
                        acc[i][j] = fmaf(av[i], bv[j], acc[i][j]);
            }
            if (t + 1 < ntiles) stage((t + 1) & 1);
            __syncthreads();
        }

        float bv[8];
#pragma unroll
        for (int j = 0; j < 8; j++) bv[j] = b1[tx * 8 + j];
#pragma unroll
        for (int i = 0; i < 8; i++) {
            float v[8];
#pragma unroll
            for (int j = 0; j < 8; j++) {
                float t = acc[i][j] + bv[j];
                v[j] = t > 0.f ? t : 0.1f * t;
            }
            float* row = Hs + (ty * 8 + i) * HS_PAD + tx * 8;
            *(float4*)(row)     = make_float4(v[0], v[1], v[2], v[3]);
            *(float4*)(row + 4) = make_float4(v[4], v[5], v[6], v[7]);
        }
    }
    __syncthreads();

    {
        auto fetchW = [&](int t) {
#pragma unroll
            for (int l = 0; l < 2; l++)
                if (w_ok[l])
                    w_reg[l] = *(const float4*)(W2 + (size_t)(t * BK + w_k[l]) * BN + w_n[l]);
        };
        auto stageW = [&](int buf) {
#pragma unroll
            for (int l = 0; l < 2; l++)
                if (w_ok[l])
                    *(float4*)(Ws + buf * (BK * BN) + w_k[l] * BN + w_n[l]) = w_reg[l];
        };

        float acc[8][8] = {};
        fetchW(0); stageW(0);
        __syncthreads();
        for (int t = 0; t < ntiles; t++) {
            if (t + 1 < ntiles) fetchW(t + 1);
            const float* Wb = Ws + (t & 1) * (BK * BN);
#pragma unroll
            for (int k = 0; k < BK; k++) {
                int kk = t * BK + k;
                float av[8];
#pragma unroll
                for (int i = 0; i < 8; i++)
                    av[i] = Hs[(ty * 8 + i) * HS_PAD + kk];
                float4 c0 = *(const float4*)(Wb + k * BN + tx * 8);
                float4 c1 = *(const float4*)(Wb + k * BN + tx * 8 + 4);
                float bv[8] = {c0.x, c0.y, c0.z, c0.w, c1.x, c1.y, c1.z, c1.w};
#pragma unroll
                for (int i = 0; i < 8; i++)
#pragma unroll
                    for (int j = 0; j < 8; j++)
                        acc[i][j] = fmaf(av[i], bv[j], acc[i][j]);
            }
            if (t + 1 < ntiles) stageW((t + 1) & 1);
            __syncthreads();
        }

        float bv[8];
#pragma unroll
        for (int j = 0; j < 8; j++) bv[j] = b2[tx * 8 + j];
#pragma unroll
        for (int i = 0; i < 8; i++) {
            int rg = block_row + ty * 8 + i;
            if (rg >= M) continue;
#pragma unroll
            for (int j = 0; j < 8; j++) {
                float v = acc[i][j] + bv[j] + src[(size_t)rg * H + tx * 8 + j];
                g_h[(size_t)rg * H + tx * 8 + j] = v;
            }
        }
    }
}

// ---------------- mma.sync readout GEMM, cp.async double-buffered ----------------
#define G2_NT 256
#define KC 64
#define KCP 72
#define TILE_HALFS (128 * KCP)
#define BUF_HALFS (4 * TILE_HALFS)
#define G2_SMEM (2 * BUF_HALFS * 2)

__device__ __forceinline__ void mma_bf16(float* c, const unsigned int* a,
                                         const unsigned int* b) {
    asm volatile(
        "mma.sync.aligned.m16n8k16.row.col.f32.bf16.bf16.f32 "
        "{%0,%1,%2,%3}, {%4,%5,%6,%7}, {%8,%9}, {%0,%1,%2,%3};\n"
        : "+f"(c[0]), "+f"(c[1]), "+f"(c[2]), "+f"(c[3])
        : "r"(a[0]), "r"(a[1]), "r"(a[2]), "r"(a[3]), "r"(b[0]), "r"(b[1]));
}

__device__ __forceinline__ void cp16(unsigned int daddr, const void* src, int srcsz) {
    asm volatile("cp.async.cg.shared.global [%0], [%1], 16, %2;"
                 :: "r"(daddr), "l"(src), "r"(srcsz));
}

// Handles rows [row_base + blockIdx*128, ...); M = global row bound.
__global__ __launch_bounds__(G2_NT, 1) void gemm2_mma_kernel(
    const float* __restrict__ br, const float* __restrict__ dst_feat,
    float* __restrict__ out, int row_base, int M)
{
    extern __shared__ __align__(16) unsigned short sh[];
    unsigned int sbase = smem_u32(sh);

    int tid = threadIdx.x;
    int wid = tid >> 5, lane = tid & 31;
    int g = lane >> 2, t = lane & 3;
    int warpM = wid & 1, warpN = wid >> 1;
    int block_row = row_base + blockIdx.x * 128;

    float acc[4][4][4];
#pragma unroll
    for (int mt = 0; mt < 4; mt++)
#pragma unroll
        for (int nt = 0; nt < 4; nt++)
#pragma unroll
            for (int q = 0; q < 4; q++) acc[mt][nt][q] = 0.f;

    auto stage = [&](int c, int buf) {
        unsigned int bb = sbase + (unsigned)buf * (BUF_HALFS * 2);
#pragma unroll
        for (int i = 0; i < 16; i++) {
            int flat = i * G2_NT + tid;
            int tile = flat >> 10;
            int idx = flat & 1023;
            int row = idx >> 3;
            int seg = idx & 7;
            unsigned int daddr = bb + (unsigned)(tile * TILE_HALFS + row * KCP + seg * 8) * 2;
            const unsigned short* src;
            int sz = 16;
            if (tile < 2) {
                int gr = block_row + row;
                const unsigned short* base = (tile == 0) ? g_agg_hi : g_agg_lo;
                src = base + (size_t)min(gr, MAX_DST - 1) * 512 + c * KC + seg * 8;
                if (gr >= M) sz = 0;
            } else {
                const unsigned short* base = (tile == 2) ? g_wt_hi : g_wt_lo;
                src = base + (size_t)row * 512 + c * KC + seg * 8;
            }
            cp16(daddr, src, sz);
        }
        asm volatile("cp.async.commit_group;" ::: "memory");
    };

    stage(0, 0);

    for (int c = 0; c < 8; c++) {
        int buf = c & 1;
        if (c < 7) stage(c + 1, (c + 1) & 1);
        if (c < 7)
            asm volatile("cp.async.wait_group 1;" ::: "memory");
        else
            asm volatile("cp.async.wait_group 0;" ::: "memory");
        __syncthreads();

        const unsigned short* sAhi = sh + (size_t)buf * BUF_HALFS;
        const unsigned short* sAlo = sAhi + TILE_HALFS;
        const unsigned short* sBhi = sAlo + TILE_HALFS;
        const unsigned short* sBlo = sBhi + TILE_HALFS;

#pragma unroll
        for (int ks = 0; ks < 4; ks++) {
            int k0 = ks * 16;
            unsigned int ahi[4][4], alo[4][4];
#pragma unroll
            for (int mt = 0; mt < 4; mt++) {
                int r0 = warpM * 64 + mt * 16 + g;
                const unsigned short* base = sAhi + (size_t)r0 * KCP + k0 + 2 * t;
                ahi[mt][0] = *(const unsigned int*)(base);
                ahi[mt][1] = *(const unsigned int*)(base + 8 * KCP);
                ahi[mt][2] = *(const unsigned int*)(base + 8);
                ahi[mt][3] = *(const unsigned int*)(base + 8 * KCP + 8);
                const unsigned short* basel = sAlo + (size_t)r0 * KCP + k0 + 2 * t;
                alo[mt][0] = *(const unsigned int*)(basel);
                alo[mt][1] = *(const unsigned int*)(basel + 8 * KCP);
                alo[mt][2] = *(const unsigned int*)(basel + 8);
                alo[mt][3] = *(const unsigned int*)(basel + 8 * KCP + 8);
            }
            unsigned int bhi[4][2], blo[4][2];
#pragma unroll
            for (int nt = 0; nt < 4; nt++) {
                int n0 = warpN * 32 + nt * 8 + g;
                const unsigned short* base = sBhi + (size_t)n0 * KCP + k0 + 2 * t;
                bhi[nt][0] = *(const unsigned int*)(base);
                bhi[nt][1] = *(const unsigned int*)(base + 8);
                const unsigned short* basel = sBlo + (size_t)n0 * KCP + k0 + 2 * t;
                blo[nt][0] = *(const unsigned int*)(basel);
                blo[nt][1] = *(const unsigned int*)(basel + 8);
            }
#pragma unroll
            for (int mt = 0; mt < 4; mt++)
#pragma unroll
                for (int nt = 0; nt < 4; nt++) {
                    mma_bf16(acc[mt][nt], ahi[mt], bhi[nt]);
                    mma_bf16(acc[mt][nt], ahi[mt], blo[nt]);
                    mma_bf16(acc[mt][nt], alo[mt], bhi[nt]);
                }
        }
        __syncthreads();
    }

#pragma unroll
    for (int nt = 0; nt < 4; nt++) {
        int n0 = warpN * 32 + nt * 8 + t * 2;
        float b0 = br[n0], b1 = br[n0 + 1];
#pragma unroll
        for (int mt = 0; mt < 4; mt++) {
            int r0 = block_row + warpM * 64 + mt * 16 + g;
            if (r0 < M) {
                float2 dd = *(const float2*)(dst_feat + (size_t)r0 * 128 + n0);
                float x0 = acc[mt][nt][0] + b0; x0 = x0 > 0.f ? x0 : 0.1f * x0;
                float x1 = acc[mt][nt][1] + b1; x1 = x1 > 0.f ? x1 : 0.1f * x1;
                float2 o; o.x = x0 + dd.x; o.y = x1 + dd.y;
                *(float2*)(out + (size_t)r0 * 128 + n0) = o;
            }
            int r1 = r0 + 8;
            if (r1 < M) {
                float2 dd = *(const float2*)(dst_feat + (size_t)r1 * 128 + n0);
                float x0 = acc[mt][nt][2] + b0; x0 = x0 > 0.f ? x0 : 0.1f * x0;
                float x1 = acc[mt][nt][3] + b1; x1 = x1 > 0.f ? x1 : 0.1f * x1;
                float2 o; o.x = x0 + dd.x; o.y = x1 + dd.y;
                *(float2*)(out + (size_t)r1 * 128 + n0) = o;
            }
        }
    }
}

// ---------------- launch ----------------
extern "C" void kernel_launch(void* const* d_in, const int* in_sizes, int n_in,
                              void* d_out, int out_size) {
    const float* src_feat = (const float*)d_in[0];
    const float* dst_feat = (const float*)d_in[1];
    const int*   edge_src = (const int*)d_in[2];
    const int*   edge_dst = (const int*)d_in[3];
    const float* W1 = (const float*)d_in[4];
    const float* b1 = (const float*)d_in[5];
    const float* W2 = (const float*)d_in[6];
    const float* b2 = (const float*)d_in[7];
    const float* Wr = (const float*)d_in[8];
    const float* br = (const float*)d_in[9];
    float* out = (float*)d_out;

    int n_src = in_sizes[0] / H;
    int n_dst = in_sizes[1] / H;
    int E     = in_sizes[2];

    int gm_src = (n_src + BM - 1) / BM;
    int nb = (n_dst + 1023) / 1024;

    // split dst rows into two halves (first half a multiple of 128)
    int P = ((n_dst / 2 + 127) / 128) * 128;
    if (P > n_dst) P = n_dst;
    int g0 = P / 128;
    int g1 = (n_dst - P + 127) / 128;

    size_t mlp_smem = (size_t)(4096 + 4608 + BM * HS_PAD) * 4;

    static cudaStream_t side = nullptr, side2 = nullptr, side3 = nullptr;
    static cudaEvent_t ev_fork = nullptr, ev_join = nullptr, ev_join2 = nullptr;
    static cudaEvent_t ev_h0 = nullptr, ev_g0 = nullptr;
    if (!side) {
        cudaStreamCreateWithFlags(&side, cudaStreamNonBlocking);
        cudaStreamCreateWithFlags(&side2, cudaStreamNonBlocking);
        cudaStreamCreateWithFlags(&side3, cudaStreamNonBlocking);
        cudaEventCreateWithFlags(&ev_fork, cudaEventDisableTiming);
        cudaEventCreateWithFlags(&ev_join, cudaEventDisableTiming);
        cudaEventCreateWithFlags(&ev_join2, cudaEventDisableTiming);
        cudaEventCreateWithFlags(&ev_h0, cudaEventDisableTiming);
        cudaEventCreateWithFlags(&ev_g0, cudaEventDisableTiming);
        cudaFuncSetAttribute(mlp_fused_kernel,
                             cudaFuncAttributeMaxDynamicSharedMemorySize,
                             (int)mlp_smem);
        cudaFuncSetAttribute(gemm2_mma_kernel,
                             cudaFuncAttributeMaxDynamicSharedMemorySize,
                             G2_SMEM);
    }

    cudaEventRecord(ev_fork, 0);
    cudaStreamWaitEvent(side, ev_fork, 0);
    cudaStreamWaitEvent(side2, ev_fork, 0);

    // side: CSR build (4 launches; scan_block re-zeros g_cnt for next replay)
    count_kernel<<<(E + 1023) / 1024, 256, 0, side>>>(edge_dst, E);
    scan_block_kernel<<<nb, 1024, 0, side>>>(n_dst);
    scan_add_kernel<<<nb, 1024, 0, side>>>(nb, n_dst);
    scatter_kernel<<<(E + 1023) / 1024, 256, 0, side>>>(edge_src, edge_dst, E);
    cudaEventRecord(ev_join, side);

    // side2: W-readout transpose/split (gates gemm2 only)
    wt_prep_kernel<<<32, 256, 0, side2>>>(Wr);
    cudaEventRecord(ev_join2, side2);

    // main: fused src MLP
    mlp_fused_kernel<<<gm_src, NTHREADS, mlp_smem>>>(src_feat, W1, b1, W2, b2, n_src);

    // join CSR, then agg half 0
    cudaStreamWaitEvent(0, ev_join, 0);
    agg_kernel<<<(P * 32 + 255) / 256, 256>>>(dst_feat, 0, P);
    cudaEventRecord(ev_h0, 0);

    // side3: gemm2 half 0 runs concurrently with agg half 1
    cudaStreamWaitEvent(side3, ev_h0, 0);
    cudaStreamWaitEvent(side3, ev_join2, 0);
    gemm2_mma_kernel<<<g0, G2_NT, G2_SMEM, side3>>>(br, dst_feat, out, 0, n_dst);
    cudaEventRecord(ev_g0, side3);

    // main: agg half 1, then gemm2 half 1
    agg_kernel<<<((n_dst - P) * 32 + 255) / 256, 256>>>(dst_feat, P, n_dst);
    cudaStreamWaitEvent(0, ev_join2, 0);
    gemm2_mma_kernel<<<g1, G2_NT, G2_SMEM>>>(br, dst_feat, out, P, n_dst);

    // join side3 back into main stream (required for graph capture)
    cudaStreamWaitEvent(0, ev_g0, 0);
}

// round 15
// speedup vs baseline: 1.0154x; 1.0154x over previous
#include <cuda_runtime.h>
#include <cuda_bf16.h>
#include <math.h>

#define H 128
#define MAX_SRC 20000
#define MAX_DST 20000
#define MAX_E   640000

// ---------------- device scratch (no runtime allocation) ----------------
__device__ float g_h[MAX_SRC * H];
// A for readout GEMM, pre-split bf16 hi/lo: [row][512] (sum|max|mean|dst)
__device__ __align__(16) unsigned short g_agg_hi[MAX_DST * 512];
__device__ __align__(16) unsigned short g_agg_lo[MAX_DST * 512];
__device__ int   g_cnt[MAX_DST];     // zero-init at load; re-zeroed by scan_full
__device__ int   g_off[MAX_DST + 1];
__device__ int   g_rank[MAX_E];      // per-edge rank within its dst bucket
__device__ int   g_perm[MAX_E];
// W_readout transposed + bf16 hi/lo split: Wt[n][k]
__device__ __align__(16) unsigned short g_wt_hi[128 * 512];
__device__ __align__(16) unsigned short g_wt_lo[128 * 512];

// ---------------- small helpers ----------------
__device__ __forceinline__ unsigned int smem_u32(const void* p) {
    unsigned int a;
    asm("{ .reg .u64 t; cvta.to.shared.u64 t, %1; cvt.u32.u64 %0, t; }"
        : "=r"(a) : "l"(p));
    return a;
}
__device__ __forceinline__ unsigned short f2bf(float x) {
    __nv_bfloat16 h = __float2bfloat16_rn(x);
    return *reinterpret_cast<unsigned short*>(&h);
}
__device__ __forceinline__ float bf2f(unsigned short u) {
    __nv_bfloat16 h = *reinterpret_cast<__nv_bfloat16*>(&u);
    return __bfloat162float(h);
}
__device__ __forceinline__ void split_store(unsigned short* oh, unsigned short* ol,
                                            float4 v) {
    unsigned short h0 = f2bf(v.x), h1 = f2bf(v.y), h2 = f2bf(v.z), h3 = f2bf(v.w);
    unsigned short l0 = f2bf(v.x - bf2f(h0));
    unsigned short l1 = f2bf(v.y - bf2f(h1));
    unsigned short l2 = f2bf(v.z - bf2f(h2));
    unsigned short l3 = f2bf(v.w - bf2f(h3));
    uint2 uh = make_uint2((unsigned)h0 | ((unsigned)h1 << 16),
                          (unsigned)h2 | ((unsigned)h3 << 16));
    uint2 ul = make_uint2((unsigned)l0 | ((unsigned)l1 << 16),
                          (unsigned)l2 | ((unsigned)l3 << 16));
    *(uint2*)oh = uh;
    *(uint2*)ol = ul;
}

// ---------------- CSR build ----------------
// count + per-edge rank (rank = atomicAdd return; the atomic cost is paid
// ONCE here, so scatter needs no atomics at all)
__global__ void count_kernel(const int* __restrict__ edge_dst, int E) {
    int i = (blockIdx.x * blockDim.x + threadIdx.x) * 4;
    if (i + 3 < E) {
        int4 d = *(const int4*)(edge_dst + i);
        int4 r;
        r.x = atomicAdd(&g_cnt[d.x], 1);
        r.y = atomicAdd(&g_cnt[d.y], 1);
        r.z = atomicAdd(&g_cnt[d.z], 1);
        r.w = atomicAdd(&g_cnt[d.w], 1);
        *(int4*)(g_rank + i) = r;
    } else {
        for (int j = 0; j < 4 && i + j < E; j++)
            g_rank[i + j] = atomicAdd(&g_cnt[edge_dst[i + j]], 1);
    }
}

// ONE-block full exclusive scan (n <= 20480): thread t owns 20 consecutive
// elements; serial sums -> block scan of 1024 partials -> write prefixes.
// Re-zeroes g_cnt so the next graph replay starts clean.
#define SCAN_PER 20
__global__ void scan_full_kernel(int n) {
    __shared__ int warp_sums[32];
    int tid = threadIdx.x, lane = tid & 31, wid = tid >> 5;
    int base = tid * SCAN_PER;
    int vals[SCAN_PER];
    int s = 0;
#pragma unroll
    for (int j = 0; j < SCAN_PER; j++) {
        int i = base + j;
        int v = (i < n) ? g_cnt[i] : 0;
        vals[j] = v;
        s += v;
    }
    // block exclusive scan of per-thread sums
    int x = s;
#pragma unroll
    for (int d = 1; d < 32; d <<= 1) {
        int t = __shfl_up_sync(0xffffffffu, x, d);
        if (lane >= d) x += t;
    }
    if (lane == 31) warp_sums[wid] = x;
    __syncthreads();
    if (wid == 0) {
        int w = warp_sums[lane];
#pragma unroll
        for (int d = 1; d < 32; d <<= 1) {
            int t = __shfl_up_sync(0xffffffffu, w, d);
            if (lane >= d) w += t;
        }
        warp_sums[lane] = w;
    }
    __syncthreads();
    int warp_pre = (wid == 0) ? 0 : warp_sums[wid - 1];
    int run = warp_pre + x - s;   // exclusive prefix for this thread
#pragma unroll
    for (int j = 0; j < SCAN_PER; j++) {
        int i = base + j;
        if (i < n) {
            g_off[i] = run;
            run += vals[j];
            g_cnt[i] = 0;
        }
    }
    if (tid == 1023) g_off[n] = warp_pre + x;   // grand total
}

// atomic-free scatter: p = off[d] + rank
__global__ void scatter_kernel(const int* __restrict__ edge_src,
                               const int* __restrict__ edge_dst, int E) {
    int i = (blockIdx.x * blockDim.x + threadIdx.x) * 4;
    if (i + 3 < E) {
        int4 d = *(const int4*)(edge_dst + i);
        int4 r = *(const int4*)(g_rank + i);
        int4 s = *(const int4*)(edge_src + i);
        g_perm[g_off[d.x] + r.x] = s.x;
        g_perm[g_off[d.y] + r.y] = s.y;
        g_perm[g_off[d.z] + r.z] = s.z;
        g_perm[g_off[d.w] + r.w] = s.w;
    } else {
        for (int j = 0; j < 4 && i + j < E; j++)
            g_perm[g_off[edge_dst[i + j]] + g_rank[i + j]] = edge_src[i + j];
    }
}

// ---------------- W-transpose + bf16 hi/lo prep ----------------
__global__ void wt_prep_kernel(const float* __restrict__ Wr) {
    int idx = blockIdx.x * blockDim.x + threadIdx.x;
    if (idx >= 128 * 64) return;
    int n = idx >> 6;
    int k0 = (idx & 63) * 8;
    unsigned short hs[8], ls[8];
#pragma unroll
    for (int i = 0; i < 8; i++) {
        float x = Wr[(size_t)(k0 + i) * 128 + n];
        hs[i] = f2bf(x);
        ls[i] = f2bf(x - bf2f(hs[i]));
    }
    uint4 uh = make_uint4((unsigned)hs[0] | ((unsigned)hs[1] << 16),
                          (unsigned)hs[2] | ((unsigned)hs[3] << 16),
                          (unsigned)hs[4] | ((unsigned)hs[5] << 16),
                          (unsigned)hs[6] | ((unsigned)hs[7] << 16));
    uint4 ul = make_uint4((unsigned)ls[0] | ((unsigned)ls[1] << 16),
                          (unsigned)ls[2] | ((unsigned)ls[3] << 16),
                          (unsigned)ls[4] | ((unsigned)ls[5] << 16),
                          (unsigned)ls[6] | ((unsigned)ls[7] << 16));
    *(uint4*)(g_wt_hi + (size_t)n * 512 + k0) = uh;
    *(uint4*)(g_wt_lo + (size_t)n * 512 + k0) = ul;
}

// ---------------- aggregation: warp per dst; emits bf16 hi/lo A rows ----------------
__global__ void agg_kernel(const float* __restrict__ dst_feat, int n_dst) {
    int warp = (blockIdx.x * blockDim.x + threadIdx.x) >> 5;
    int lane = threadIdx.x & 31;
    if (warp >= n_dst) return;
    int d = warp;
    int beg = g_off[d], end = g_off[d + 1];
    const float4* __restrict__ hv = (const float4*)g_h;

    float4 sum = make_float4(0.f, 0.f, 0.f, 0.f);
    float4 mx  = make_float4(-3.4e38f, -3.4e38f, -3.4e38f, -3.4e38f);

    int e = beg;
    for (; e + 7 < end; e += 8) {
        int s[8];
#pragma unroll
        for (int j = 0; j < 8; j++) s[j] = g_perm[e + j];
        float4 v[8];
#pragma unroll
        for (int j = 0; j < 8; j++) v[j] = hv[s[j] * 32 + lane];
#pragma unroll
        for (int j = 0; j < 8; j++) {
            sum.x += v[j].x; sum.y += v[j].y; sum.z += v[j].z; sum.w += v[j].w;
            mx.x = fmaxf(mx.x, v[j].x); mx.y = fmaxf(mx.y, v[j].y);
            mx.z = fmaxf(mx.z, v[j].z); mx.w = fmaxf(mx.w, v[j].w);
        }
    }
    for (; e < end; e++) {
        int s0 = g_perm[e];
        float4 v0 = hv[s0 * 32 + lane];
        sum.x += v0.x; sum.y += v0.y; sum.z += v0.z; sum.w += v0.w;
        mx.x = fmaxf(mx.x, v0.x); mx.y = fmaxf(mx.y, v0.y);
        mx.z = fmaxf(mx.z, v0.z); mx.w = fmaxf(mx.w, v0.w);
    }

    int cnt = end - beg;
    if (cnt == 0) mx = make_float4(0.f, 0.f, 0.f, 0.f);
    float inv = 1.0f / (float)(cnt > 0 ? cnt : 1);
    float4 mean = make_float4(sum.x * inv, sum.y * inv, sum.z * inv, sum.w * inv);
    float4 dv = ((const float4*)dst_feat)[d * 32 + lane];

    unsigned short* oh = g_agg_hi + (size_t)d * 512;
    unsigned short* ol = g_agg_lo + (size_t)d * 512;
    split_store(oh +   0 + lane * 4, ol +   0 + lane * 4, sum);
    split_store(oh + 128 + lane * 4, ol + 128 + lane * 4, mx);
    split_store(oh + 256 + lane * 4, ol + 256 + lane * 4, mean);
    split_store(oh + 384 + lane * 4, ol + 384 + lane * 4, dv);
}

// ---------------- tiling constants (FFMA MLP) ----------------
#define BM 144
#define BN 128
#define BK 16
#define NTHREADS 288
#define HS_PAD 136

// ---------------- fused MLP: h = src + lrelu(src@W1+b1)@W2 + b2 ----------------
__global__ __launch_bounds__(NTHREADS, 1) void mlp_fused_kernel(
    const float* __restrict__ src, const float* __restrict__ W1,
    const float* __restrict__ b1, const float* __restrict__ W2,
    const float* __restrict__ b2, int M)
{
    extern __shared__ float smem[];
    float* Ws = smem;                       // [2][BK][BN]
    float* As = smem + 4096;                // [2][BK][BM]
    float* Hs = smem + 4096 + 4608;         // [BM][HS_PAD]

    int tid = threadIdx.x;
    int block_row = blockIdx.x * BM;
    int tx = tid & 15, ty = tid >> 4;

    int a_row[2], a_col[2], w_k[2], w_n[2];
    bool w_ok[2];
#pragma unroll
    for (int l = 0; l < 2; l++) {
        int flat = tid + l * NTHREADS;
        a_row[l] = flat >> 2;
        a_col[l] = (flat & 3) * 4;
        w_ok[l] = flat < 512;
        int wf = w_ok[l] ? flat : 0;
        w_k[l] = wf >> 5;
        w_n[l] = (wf & 31) * 4;
    }

    float4 a_reg[2], w_reg[2];
    const int ntiles = H / BK;

    {
        auto fetch = [&](int t) {
#pragma unroll
            for (int l = 0; l < 2; l++) {
                int rg = block_row + a_row[l];
                a_reg[l] = (rg < M) ? *(const float4*)(src + (size_t)rg * H + t * BK + a_col[l])
                                    : make_float4(0.f, 0.f, 0.f, 0.f);
                if (w_ok[l])
                    w_reg[l] = *(const float4*)(W1 + (size_t)(t * BK + w_k[l]) * BN + w_n[l]);
            }
        };
        auto stage = [&](int buf) {
#pragma unroll
            for (int l = 0; l < 2; l++) {
                float* Ab = As + buf * (BK * BM);
                Ab[(a_col[l] + 0) * BM + a_row[l]] = a_reg[l].x;
                Ab[(a_col[l] + 1) * BM + a_row[l]] = a_reg[l].y;
                Ab[(a_col[l] + 2) * BM + a_row[l]] = a_reg[l].z;
                Ab[(a_col[l] + 3) * BM + a_row[l]] = a_reg[l].w;
                if (w_ok[l])
                    *(float4*)(Ws + buf * (BK * BN) + w_k[l] * BN + w_n[l]) = w_reg[l];
            }
        };

        float acc[8][8] = {};
        fetch(0); stage(0);
        __syncthreads();
        for (int t = 0; t < ntiles; t++) {
            if (t + 1 < ntiles) fetch(t + 1);
            const float* Ab = As + (t & 1) * (BK * BM);
            const float* Wb = Ws + (t & 1) * (BK * BN);
#pragma unroll
            for (int k = 0; k < BK; k++) {
                float4 a0 = *(const float4*)(Ab + k * BM + ty * 8);
                float4 a1 = *(const float4*)(Ab + k * BM + ty * 8 + 4);
                float4 c0 = *(const float4*)(Wb + k * BN + tx * 8);
                float4 c1 = *(const float4*)(Wb + k * BN + tx * 8 + 4);
                float av[8] = {a0.x, a0.y, a0.z, a0.w, a1.x, a1.y, a1.z, a1.w};
                float bv[8] = {c0.x, c0.y, c0.z, c0.w, c1.x, c1.y, c1.z, c1.w};
#pragma unroll
                for (int i = 0; i < 8; i++)
#pragma unroll
                    for (int j = 0; j < 8; j++)
                        acc[i][j] = fmaf(av[i], bv[j], acc[i][j]);
            }
            if (t + 1 < ntiles) stage((t + 1) & 1);
            __syncthreads();
        }

        float bv[8];
#pragma unroll
        for (int j = 0; j < 8; j++) bv[j] = b1[tx * 8 + j];
#pragma unroll
        for (int i = 0; i < 8; i++) {
            float v[8];
#pragma unroll
            for (int j = 0; j < 8; j++) {
                float t = acc[i][j] + bv[j];
                v[j] = t > 0.f ? t : 0.1f * t;
            }
            float* row = Hs + (ty * 8 + i) * HS_PAD + tx * 8;
            *(float4*)(row)     = make_float4(v[0], v[1], v[2], v[3]);
            *(float4*)(row + 4) = make_float4(v[4], v[5], v[6], v[7]);
        }
    }
    __syncthreads();

    {
        auto fetchW = [&](int t) {
#pragma unroll
            for (int l = 0; l < 2; l++)
                if (w_ok[l])
                    w_reg[l] = *(const float4*)(W2 + (size_t)(t * BK + w_k[l]) * BN + w_n[l]);
        };
        auto stageW = [&](int buf) {
#pragma unroll
            for (int l = 0; l < 2; l++)
                if (w_ok[l])
                    *(float4*)(Ws + buf * (BK * BN) + w_k[l] * BN + w_n[l]) = w_reg[l];
        };

        float acc[8][8] = {};
        fetchW(0); stageW(0);
        __syncthreads();
        for (int t = 0; t < ntiles; t++) {
            if (t + 1 < ntiles) fetchW(t + 1);
            const float* Wb = Ws + (t & 1) * (BK * BN);
#pragma unroll
            for (int k = 0; k < BK; k++) {
                int kk = t * BK + k;
                float av[8];
#pragma unroll
                for (int i = 0; i < 8; i++)
                    av[i] = Hs[(ty * 8 + i) * HS_PAD + kk];
                float4 c0 = *(const float4*)(Wb + k * BN + tx * 8);
                float4 c1 = *(const float4*)(Wb + k * BN + tx * 8 + 4);
                float bv[8] = {c0.x, c0.y, c0.z, c0.w, c1.x, c1.y, c1.z, c1.w};
#pragma unroll
                for (int i = 0; i < 8; i++)
#pragma unroll
                    for (int j = 0; j < 8; j++)
                        acc[i][j] = fmaf(av[i], bv[j], acc[i][j]);
            }
            if (t + 1 < ntiles) stageW((t + 1) & 1);
            __syncthreads();
        }

        float bv[8];
#pragma unroll
        for (int j = 0; j < 8; j++) bv[j] = b2[tx * 8 + j];
#pragma unroll
        for (int i = 0; i < 8; i++) {
            int rg = block_row + ty * 8 + i;
            if (rg >= M) continue;
#pragma unroll
            for (int j = 0; j < 8; j++) {
                float v = acc[i][j] + bv[j] + src[(size_t)rg * H + tx * 8 + j];
                g_h[(size_t)rg * H + tx * 8 + j] = v;
            }
        }
    }
}

// ---------------- mma.sync readout GEMM, cp.async double-buffered ----------------
#define G2_NT 256
#define KC 64
#define KCP 72
#define TILE_HALFS (128 * KCP)
#define BUF_HALFS (4 * TILE_HALFS)
#define G2_SMEM (2 * BUF_HALFS * 2)

__device__ __forceinline__ void mma_bf16(float* c, const unsigned int* a,
                                         const unsigned int* b) {
    asm volatile(
        "mma.sync.aligned.m16n8k16.row.col.f32.bf16.bf16.f32 "
        "{%0,%1,%2,%3}, {%4,%5,%6,%7}, {%8,%9}, {%0,%1,%2,%3};\n"
        : "+f"(c[0]), "+f"(c[1]), "+f"(c[2]), "+f"(c[3])
        : "r"(a[0]), "r"(a[1]), "r"(a[2]), "r"(a[3]), "r"(b[0]), "r"(b[1]));
}

__device__ __forceinline__ void cp16(unsigned int daddr, const void* src, int srcsz) {
    asm volatile("cp.async.cg.shared.global [%0], [%1], 16, %2;"
                 :: "r"(daddr), "l"(src), "r"(srcsz));
}

__global__ __launch_bounds__(G2_NT, 1) void gemm2_mma_kernel(
    const float* __restrict__ br, const float* __restrict__ dst_feat,
    float* __restrict__ out, int M)
{
    extern __shared__ __align__(16) unsigned short sh[];
    unsigned int sbase = smem_u32(sh);

    int tid = threadIdx.x;
    int wid = tid >> 5, lane = tid & 31;
    int g = lane >> 2, t = lane & 3;
    int warpM = wid & 1, warpN = wid >> 1;
    int block_row = blockIdx.x * 128;

    float acc[4][4][4];
#pragma unroll
    for (int mt = 0; mt < 4; mt++)
#pragma unroll
        for (int nt = 0; nt < 4; nt++)
#pragma unroll
            for (int q = 0; q < 4; q++) acc[mt][nt][q] = 0.f;

    auto stage = [&](int c, int buf) {
        unsigned int bb = sbase + (unsigned)buf * (BUF_HALFS * 2);
#pragma unroll
        for (int i = 0; i < 16; i++) {
            int flat = i * G2_NT + tid;
            int tile = flat >> 10;
            int idx = flat & 1023;
            int row = idx >> 3;
            int seg = idx & 7;
            unsigned int daddr = bb + (unsigned)(tile * TILE_HALFS + row * KCP + seg * 8) * 2;
            const unsigned short* src;
            int sz = 16;
            if (tile < 2) {
                int gr = block_row + row;
                const unsigned short* base = (tile == 0) ? g_agg_hi : g_agg_lo;
                src = base + (size_t)min(gr, MAX_DST - 1) * 512 + c * KC + seg * 8;
                if (gr >= M) sz = 0;
            } else {
                const unsigned short* base = (tile == 2) ? g_wt_hi : g_wt_lo;
                src = base + (size_t)row * 512 + c * KC + seg * 8;
            }
            cp16(daddr, src, sz);
        }
        asm volatile("cp.async.commit_group;" ::: "memory");
    };

    stage(0, 0);

    for (int c = 0; c < 8; c++) {
        int buf = c & 1;
        if (c < 7) stage(c + 1, (c + 1) & 1);
        if (c < 7)
            asm volatile("cp.async.wait_group 1;" ::: "memory");
        else
            asm volatile("cp.async.wait_group 0;" ::: "memory");
        __syncthreads();

        const unsigned short* sAhi = sh + (size_t)buf * BUF_HALFS;
        const unsigned short* sAlo = sAhi + TILE_HALFS;
        const unsigned short* sBhi = sAlo + TILE_HALFS;
        const unsigned short* sBlo = sBhi + TILE_HALFS;

#pragma unroll
        for (int ks = 0; ks < 4; ks++) {
            int k0 = ks * 16;
            unsigned int ahi[4][4], alo[4][4];
#pragma unroll
            for (int mt = 0; mt < 4; mt++) {
                int r0 = warpM * 64 + mt * 16 + g;
                const unsigned short* base = sAhi + (size_t)r0 * KCP + k0 + 2 * t;
                ahi[mt][0] = *(const unsigned int*)(base);
                ahi[mt][1] = *(const unsigned int*)(base + 8 * KCP);
                ahi[mt][2] = *(const unsigned int*)(base + 8);
                ahi[mt][3] = *(const unsigned int*)(base + 8 * KCP + 8);
                const unsigned short* basel = sAlo + (size_t)r0 * KCP + k0 + 2 * t;
                alo[mt][0] = *(const unsigned int*)(basel);
                alo[mt][1] = *(const unsigned int*)(basel + 8 * KCP);
                alo[mt][2] = *(const unsigned int*)(basel + 8);
                alo[mt][3] = *(const unsigned int*)(basel + 8 * KCP + 8);
            }
            unsigned int bhi[4][2], blo[4][2];
#pragma unroll
            for (int nt = 0; nt < 4; nt++) {
                int n0 = warpN * 32 + nt * 8 + g;
                const unsigned short* base = sBhi + (size_t)n0 * KCP + k0 + 2 * t;
                bhi[nt][0] = *(const unsigned int*)(base);
                bhi[nt][1] = *(const unsigned int*)(base + 8);
                const unsigned short* basel = sBlo + (size_t)n0 * KCP + k0 + 2 * t;
                blo[nt][0] = *(const unsigned int*)(basel);
                blo[nt][1] = *(const unsigned int*)(basel + 8);
            }
#pragma unroll
            for (int mt = 0; mt < 4; mt++)
#pragma unroll
                for (int nt = 0; nt < 4; nt++) {
                    mma_bf16(acc[mt][nt], ahi[mt], bhi[nt]);
                    mma_bf16(acc[mt][nt], ahi[mt], blo[nt]);
                    mma_bf16(acc[mt][nt], alo[mt], bhi[nt]);
                }
        }
        __syncthreads();
    }

#pragma unroll
    for (int nt = 0; nt < 4; nt++) {
        int n0 = warpN * 32 + nt * 8 + t * 2;
        float b0 = br[n0], b1 = br[n0 + 1];
#pragma unroll
        for (int mt = 0; mt < 4; mt++) {
            int r0 = block_row + warpM * 64 + mt * 16 + g;
            if (r0 < M) {
                float2 dd = *(const float2*)(dst_feat + (size_t)r0 * 128 + n0);
                float x0 = acc[mt][nt][0] + b0; x0 = x0 > 0.f ? x0 : 0.1f * x0;
                float x1 = acc[mt][nt][1] + b1; x1 = x1 > 0.f ? x1 : 0.1f * x1;
                float2 o; o.x = x0 + dd.x; o.y = x1 + dd.y;
                *(float2*)(out + (size_t)r0 * 128 + n0) = o;
            }
            int r1 = r0 + 8;
            if (r1 < M) {
                float2 dd = *(const float2*)(dst_feat + (size_t)r1 * 128 + n0);
                float x0 = acc[mt][nt][2] + b0; x0 = x0 > 0.f ? x0 : 0.1f * x0;
                float x1 = acc[mt][nt][3] + b1; x1 = x1 > 0.f ? x1 : 0.1f * x1;
                float2 o; o.x = x0 + dd.x; o.y = x1 + dd.y;
                *(float2*)(out + (size_t)r1 * 128 + n0) = o;
            }
        }
    }
}

// ---------------- launch ----------------
extern "C" void kernel_launch(void* const* d_in, const int* in_sizes, int n_in,
                              void* d_out, int out_size) {
    const float* src_feat = (const float*)d_in[0];
    const float* dst_feat = (const float*)d_in[1];
    const int*   edge_src = (const int*)d_in[2];
    const int*   edge_dst = (const int*)d_in[3];
    const float* W1 = (const float*)d_in[4];
    const float* b1 = (const float*)d_in[5];
    const float* W2 = (const float*)d_in[6];
    const float* b2 = (const float*)d_in[7];
    const float* Wr = (const float*)d_in[8];
    const float* br = (const float*)d_in[9];
    float* out = (float*)d_out;

    int n_src = in_sizes[0] / H;
    int n_dst = in_sizes[1] / H;
    int E     = in_sizes[2];

    int gm_src = (n_src + BM - 1) / BM;
    int gm_tc  = (n_dst + 127) / 128;

    size_t mlp_smem = (size_t)(4096 + 4608 + BM * HS_PAD) * 4;

    static cudaStream_t side = nullptr, side2 = nullptr;
    static cudaEvent_t ev_fork = nullptr, ev_join = nullptr, ev_join2 = nullptr;
    if (!side) {
        cudaStreamCreateWithFlags(&side, cudaStreamNonBlocking);
        cudaStreamCreateWithFlags(&side2, cudaStreamNonBlocking);
        cudaEventCreateWithFlags(&ev_fork, cudaEventDisableTiming);
        cudaEventCreateWithFlags(&ev_join, cudaEventDisableTiming);
        cudaEventCreateWithFlags(&ev_join2, cudaEventDisableTiming);
        cudaFuncSetAttribute(mlp_fused_kernel,
                             cudaFuncAttributeMaxDynamicSharedMemorySize,
                             (int)mlp_smem);
        cudaFuncSetAttribute(gemm2_mma_kernel,
                             cudaFuncAttributeMaxDynamicSharedMemorySize,
                             G2_SMEM);
    }

    cudaEventRecord(ev_fork, 0);
    cudaStreamWaitEvent(side, ev_fork, 0);
    cudaStreamWaitEvent(side2, ev_fork, 0);

    // side: CSR build — count(+rank), ONE scan launch, atomic-free scatter
    count_kernel<<<(E + 1023) / 1024, 256, 0, side>>>(edge_dst, E);
    scan_full_kernel<<<1, 1024, 0, side>>>(n_dst);
    scatter_kernel<<<(E + 1023) / 1024, 256, 0, side>>>(edge_src, edge_dst, E);
    cudaEventRecord(ev_join, side);

    // side2: W-readout transpose/split (gates gemm2 only)
    wt_prep_kernel<<<32, 256, 0, side2>>>(Wr);
    cudaEventRecord(ev_join2, side2);

    // main: fused src MLP
    mlp_fused_kernel<<<gm_src, NTHREADS, mlp_smem>>>(src_feat, W1, b1, W2, b2, n_src);

    // join CSR, then aggregation
    cudaStreamWaitEvent(0, ev_join, 0);
    agg_kernel<<<(n_dst * 32 + 255) / 256, 256>>>(dst_feat, n_dst);

    // readout GEMM
    cudaStreamWaitEvent(0, ev_join2, 0);
    gemm2_mma_kernel<<<gm_tc, G2_NT, G2_SMEM>>>(br, dst_feat, out, n_dst);
}

// round 16
// speedup vs baseline: 1.1079x; 1.0911x over previous
#include <cuda_runtime.h>
#include <cuda_bf16.h>
#include <math.h>

#define H 128
#define MAX_SRC 20000
#define MAX_DST 20000
#define MAX_E   640000

// ---------------- device scratch (no runtime allocation) ----------------
__device__ float g_h[MAX_SRC * H];
__device__ __align__(16) unsigned short g_agg_hi[MAX_DST * 512];
__device__ __align__(16) unsigned short g_agg_lo[MAX_DST * 512];
__device__ int   g_cnt[MAX_DST];     // zero-init at load; re-zeroed by scan_full
__device__ int   g_off[MAX_DST + 1];
__device__ int   g_rank[MAX_E];
__device__ int   g_perm[MAX_E];
// pre-split weights: Wt[n][k] bf16 hi/lo
__device__ __align__(16) unsigned short g_wt_hi[128 * 512];
__device__ __align__(16) unsigned short g_wt_lo[128 * 512];
__device__ __align__(16) unsigned short g_w1t_hi[128 * 128];
__device__ __align__(16) unsigned short g_w1t_lo[128 * 128];
__device__ __align__(16) unsigned short g_w2t_hi[128 * 128];
__device__ __align__(16) unsigned short g_w2t_lo[128 * 128];

// ---------------- small helpers ----------------
__device__ __forceinline__ unsigned int smem_u32(const void* p) {
    unsigned int a;
    asm("{ .reg .u64 t; cvta.to.shared.u64 t, %1; cvt.u32.u64 %0, t; }"
        : "=r"(a) : "l"(p));
    return a;
}
__device__ __forceinline__ unsigned short f2bf(float x) {
    __nv_bfloat16 h = __float2bfloat16_rn(x);
    return *reinterpret_cast<unsigned short*>(&h);
}
__device__ __forceinline__ float bf2f(unsigned short u) {
    __nv_bfloat16 h = *reinterpret_cast<__nv_bfloat16*>(&u);
    return __bfloat162float(h);
}
__device__ __forceinline__ void split_store(unsigned short* oh, unsigned short* ol,
                                            float4 v) {
    unsigned short h0 = f2bf(v.x), h1 = f2bf(v.y), h2 = f2bf(v.z), h3 = f2bf(v.w);
    unsigned short l0 = f2bf(v.x - bf2f(h0));
    unsigned short l1 = f2bf(v.y - bf2f(h1));
    unsigned short l2 = f2bf(v.z - bf2f(h2));
    unsigned short l3 = f2bf(v.w - bf2f(h3));
    uint2 uh = make_uint2((unsigned)h0 | ((unsigned)h1 << 16),
                          (unsigned)h2 | ((unsigned)h3 << 16));
    uint2 ul = make_uint2((unsigned)l0 | ((unsigned)l1 << 16),
                          (unsigned)l2 | ((unsigned)l3 << 16));
    *(uint2*)oh = uh;
    *(uint2*)ol = ul;
}
__device__ __forceinline__ void split2(float x0, float x1,
                                       unsigned int& uh, unsigned int& ul) {
    unsigned short h0 = f2bf(x0), h1 = f2bf(x1);
    unsigned short l0 = f2bf(x0 - bf2f(h0));
    unsigned short l1 = f2bf(x1 - bf2f(h1));
    uh = (unsigned)h0 | ((unsigned)h1 << 16);
    ul = (unsigned)l0 | ((unsigned)l1 << 16);
}
// split 8 consecutive floats into uint4 hi / uint4 lo
__device__ __forceinline__ void split8(const float* v, uint4& uh, uint4& ul) {
    unsigned short hs[8], ls[8];
#pragma unroll
    for (int i = 0; i < 8; i++) {
        hs[i] = f2bf(v[i]);
        ls[i] = f2bf(v[i] - bf2f(hs[i]));
    }
    uh = make_uint4((unsigned)hs[0] | ((unsigned)hs[1] << 16),
                    (unsigned)hs[2] | ((unsigned)hs[3] << 16),
                    (unsigned)hs[4] | ((unsigned)hs[5] << 16),
                    (unsigned)hs[6] | ((unsigned)hs[7] << 16));
    ul = make_uint4((unsigned)ls[0] | ((unsigned)ls[1] << 16),
                    (unsigned)ls[2] | ((unsigned)ls[3] << 16),
                    (unsigned)ls[4] | ((unsigned)ls[5] << 16),
                    (unsigned)ls[6] | ((unsigned)ls[7] << 16));
}

// ---------------- CSR build ----------------
__global__ void count_kernel(const int* __restrict__ edge_dst, int E) {
    int i = (blockIdx.x * blockDim.x + threadIdx.x) * 4;
    if (i + 3 < E) {
        int4 d = *(const int4*)(edge_dst + i);
        int4 r;
        r.x = atomicAdd(&g_cnt[d.x], 1);
        r.y = atomicAdd(&g_cnt[d.y], 1);
        r.z = atomicAdd(&g_cnt[d.z], 1);
        r.w = atomicAdd(&g_cnt[d.w], 1);
        *(int4*)(g_rank + i) = r;
    } else {
        for (int j = 0; j < 4 && i + j < E; j++)
            g_rank[i + j] = atomicAdd(&g_cnt[edge_dst[i + j]], 1);
    }
}

#define SCAN_PER 20
__global__ void scan_full_kernel(int n) {
    __shared__ int warp_sums[32];
    int tid = threadIdx.x, lane = tid & 31, wid = tid >> 5;
    int base = tid * SCAN_PER;
    int vals[SCAN_PER];
    int s = 0;
#pragma unroll
    for (int j = 0; j < SCAN_PER; j++) {
        int i = base + j;
        int v = (i < n) ? g_cnt[i] : 0;
        vals[j] = v;
        s += v;
    }
    int x = s;
#pragma unroll
    for (int d = 1; d < 32; d <<= 1) {
        int t = __shfl_up_sync(0xffffffffu, x, d);
        if (lane >= d) x += t;
    }
    if (lane == 31) warp_sums[wid] = x;
    __syncthreads();
    if (wid == 0) {
        int w = warp_sums[lane];
#pragma unroll
        for (int d = 1; d < 32; d <<= 1) {
            int t = __shfl_up_sync(0xffffffffu, w, d);
            if (lane >= d) w += t;
        }
        warp_sums[lane] = w;
    }
    __syncthreads();
    int warp_pre = (wid == 0) ? 0 : warp_sums[wid - 1];
    int run = warp_pre + x - s;
#pragma unroll
    for (int j = 0; j < SCAN_PER; j++) {
        int i = base + j;
        if (i < n) {
            g_off[i] = run;
            run += vals[j];
            g_cnt[i] = 0;
        }
    }
    if (tid == 1023) g_off[n] = warp_pre + x;
}

__global__ void scatter_kernel(const int* __restrict__ edge_src,
                               const int* __restrict__ edge_dst, int E) {
    int i = (blockIdx.x * blockDim.x + threadIdx.x) * 4;
    if (i + 3 < E) {
        int4 d = *(const int4*)(edge_dst + i);
        int4 r = *(const int4*)(g_rank + i);
        int4 s = *(const int4*)(edge_src + i);
        g_perm[g_off[d.x] + r.x] = s.x;
        g_perm[g_off[d.y] + r.y] = s.y;
        g_perm[g_off[d.z] + r.z] = s.z;
        g_perm[g_off[d.w] + r.w] = s.w;
    } else {
        for (int j = 0; j < 4 && i + j < E; j++)
            g_perm[g_off[edge_dst[i + j]] + g_rank[i + j]] = edge_src[i + j];
    }
}

// ---------------- weight transpose + bf16 hi/lo prep (Wr, W1, W2) ----------------
__global__ void w_prep_kernel(const float* __restrict__ Wr,
                              const float* __restrict__ W1,
                              const float* __restrict__ W2) {
    int idx = blockIdx.x * blockDim.x + threadIdx.x;   // 12288 total
    if (idx < 8192) {                                  // Wr: [512,128] -> Wt[n][512]
        int n = idx >> 6;
        int k0 = (idx & 63) * 8;
        float v[8];
#pragma unroll
        for (int i = 0; i < 8; i++) v[i] = Wr[(size_t)(k0 + i) * 128 + n];
        uint4 uh, ul;
        split8(v, uh, ul);
        *(uint4*)(g_wt_hi + (size_t)n * 512 + k0) = uh;
        *(uint4*)(g_wt_lo + (size_t)n * 512 + k0) = ul;
    } else if (idx < 8192 + 2048) {                    // W1: [128,128] -> W1t[n][128]
        int id = idx - 8192;
        int n = id >> 4;
        int k0 = (id & 15) * 8;
        float v[8];
#pragma unroll
        for (int i = 0; i < 8; i++) v[i] = W1[(size_t)(k0 + i) * 128 + n];
        uint4 uh, ul;
        split8(v, uh, ul);
        *(uint4*)(g_w1t_hi + (size_t)n * 128 + k0) = uh;
        *(uint4*)(g_w1t_lo + (size_t)n * 128 + k0) = ul;
    } else if (idx < 8192 + 4096) {                    // W2
        int id = idx - 8192 - 2048;
        int n = id >> 4;
        int k0 = (id & 15) * 8;
        float v[8];
#pragma unroll
        for (int i = 0; i < 8; i++) v[i] = W2[(size_t)(k0 + i) * 128 + n];
        uint4 uh, ul;
        split8(v, uh, ul);
        *(uint4*)(g_w2t_hi + (size_t)n * 128 + k0) = uh;
        *(uint4*)(g_w2t_lo + (size_t)n * 128 + k0) = ul;
    }
}

// ---------------- aggregation: warp per dst; emits bf16 hi/lo A rows ----------------
__global__ void agg_kernel(const float* __restrict__ dst_feat, int n_dst) {
    int warp = (blockIdx.x * blockDim.x + threadIdx.x) >> 5;
    int lane = threadIdx.x & 31;
    if (warp >= n_dst) return;
    int d = warp;
    int beg = g_off[d], end = g_off[d + 1];
    const float4* __restrict__ hv = (const float4*)g_h;

    float4 sum = make_float4(0.f, 0.f, 0.f, 0.f);
    float4 mx  = make_float4(-3.4e38f, -3.4e38f, -3.4e38f, -3.4e38f);

    int e = beg;
    for (; e + 7 < end; e += 8) {
        int s[8];
#pragma unroll
        for (int j = 0; j < 8; j++) s[j] = g_perm[e + j];
        float4 v[8];
#pragma unroll
        for (int j = 0; j < 8; j++) v[j] = hv[s[j] * 32 + lane];
#pragma unroll
        for (int j = 0; j < 8; j++) {
            sum.x += v[j].x; sum.y += v[j].y; sum.z += v[j].z; sum.w += v[j].w;
            mx.x = fmaxf(mx.x, v[j].x); mx.y = fmaxf(mx.y, v[j].y);
            mx.z = fmaxf(mx.z, v[j].z); mx.w = fmaxf(mx.w, v[j].w);
        }
    }
    for (; e < end; e++) {
        int s0 = g_perm[e];
        float4 v0 = hv[s0 * 32 + lane];
        sum.x += v0.x; sum.y += v0.y; sum.z += v0.z; sum.w += v0.w;
        mx.x = fmaxf(mx.x, v0.x); mx.y = fmaxf(mx.y, v0.y);
        mx.z = fmaxf(mx.z, v0.z); mx.w = fmaxf(mx.w, v0.w);
    }

    int cnt = end - beg;
    if (cnt == 0) mx = make_float4(0.f, 0.f, 0.f, 0.f);
    float inv = 1.0f / (float)(cnt > 0 ? cnt : 1);
    float4 mean = make_float4(sum.x * inv, sum.y * inv, sum.z * inv, sum.w * inv);
    float4 dv = ((const float4*)dst_feat)[d * 32 + lane];

    unsigned short* oh = g_agg_hi + (size_t)d * 512;
    unsigned short* ol = g_agg_lo + (size_t)d * 512;
    split_store(oh +   0 + lane * 4, ol +   0 + lane * 4, sum);
    split_store(oh + 128 + lane * 4, ol + 128 + lane * 4, mx);
    split_store(oh + 256 + lane * 4, ol + 256 + lane * 4, mean);
    split_store(oh + 384 + lane * 4, ol + 384 + lane * 4, dv);
}

// ---------------- shared mma helpers ----------------
__device__ __forceinline__ void mma_bf16(float* c, const unsigned int* a,
                                         const unsigned int* b) {
    asm volatile(
        "mma.sync.aligned.m16n8k16.row.col.f32.bf16.bf16.f32 "
        "{%0,%1,%2,%3}, {%4,%5,%6,%7}, {%8,%9}, {%0,%1,%2,%3};\n"
        : "+f"(c[0]), "+f"(c[1]), "+f"(c[2]), "+f"(c[3])
        : "r"(a[0]), "r"(a[1]), "r"(a[2]), "r"(a[3]), "r"(b[0]), "r"(b[1]));
}
__device__ __forceinline__ void cp16(unsigned int daddr, const void* src, int srcsz) {
    asm volatile("cp.async.cg.shared.global [%0], [%1], 16, %2;"
                 :: "r"(daddr), "l"(src), "r"(srcsz));
}

// ---------------- mma.sync fused MLP ----------------
// h = src + lrelu(src@W1 + b1)@W2 + b2, 3-term bf16 per GEMM, all in one kernel.
// Block = 128 rows, 256 threads (8 warps: 2M x 4N), K=128 unchunked.
#define KCP2 136
#define TILE2 (128 * KCP2)                 // halfs per tile
#define MLP_SMEM (4 * TILE2 * 2)           // sA(hi,lo) + sB(hi,lo) = 139264 B

__global__ __launch_bounds__(256, 1) void mlp_mma_kernel(
    const float* __restrict__ src, const float* __restrict__ b1v,
    const float* __restrict__ b2v, int M)
{
    extern __shared__ __align__(16) unsigned short sh[];
    unsigned short* sA = sh;               // hi tile, then lo tile (reused for hidden)
    unsigned short* sB = sh + 2 * TILE2;   // hi tile, then lo tile (W1 then W2)
    unsigned int sbase = smem_u32(sh);

    int tid = threadIdx.x;
    int wid = tid >> 5, lane = tid & 31;
    int g = lane >> 2, t = lane & 3;
    int warpM = wid & 1, warpN = wid >> 1;
    int block_row = blockIdx.x * 128;

    // ---- stage B = W1t hi/lo via cp.async ----
    {
        unsigned int bb = sbase + (unsigned)(2 * TILE2) * 2;
#pragma unroll
        for (int i = 0; i < 16; i++) {
            int flat = i * 256 + tid;          // 0..4095
            int tile = flat >> 11;             // 0..1
            int idx = flat & 2047;
            int row = idx >> 4;
            int seg = idx & 15;
            unsigned int daddr = bb + (unsigned)(tile * TILE2 + row * KCP2 + seg * 8) * 2;
            const unsigned short* p = ((tile == 0) ? g_w1t_hi : g_w1t_lo)
                                      + (size_t)row * 128 + seg * 8;
            cp16(daddr, p, 16);
        }
        asm volatile("cp.async.commit_group;" ::: "memory");
    }

    // ---- stage A = split(src rows) ----
    {
        int arow = tid >> 1;
        int ak = (tid & 1) * 64;
        int gr = block_row + arow;
#pragma unroll
        for (int seg = 0; seg < 8; seg++) {
            int k0 = ak + seg * 8;
            float v[8];
            if (gr < M) {
                float4 p0 = *(const float4*)(src + (size_t)gr * 128 + k0);
                float4 p1 = *(const float4*)(src + (size_t)gr * 128 + k0 + 4);
                v[0]=p0.x; v[1]=p0.y; v[2]=p0.z; v[3]=p0.w;
                v[4]=p1.x; v[5]=p1.y; v[6]=p1.z; v[7]=p1.w;
            } else {
#pragma unroll
                for (int i = 0; i < 8; i++) v[i] = 0.f;
            }
            uint4 uh, ul;
            split8(v, uh, ul);
            *(uint4*)(sA + arow * KCP2 + k0) = uh;
            *(uint4*)(sA + TILE2 + arow * KCP2 + k0) = ul;
        }
    }
    asm volatile("cp.async.wait_group 0;" ::: "memory");
    __syncthreads();

    float acc[4][4][4];
#pragma unroll
    for (int mt = 0; mt < 4; mt++)
#pragma unroll
        for (int nt = 0; nt < 4; nt++)
#pragma unroll
            for (int q = 0; q < 4; q++) acc[mt][nt][q] = 0.f;

    // ---- MMA loop (shared by both phases via lambda) ----
    auto mma_phase = [&]() {
        const unsigned short* sAhi = sA;
        const unsigned short* sAlo = sA + TILE2;
        const unsigned short* sBhi = sB;
        const unsigned short* sBlo = sB + TILE2;
#pragma unroll
        for (int ks = 0; ks < 8; ks++) {
            int k0 = ks * 16;
            unsigned int ahi[4][4], alo[4][4];
#pragma unroll
            for (int mt = 0; mt < 4; mt++) {
                int r0 = warpM * 64 + mt * 16 + g;
                const unsigned short* base = sAhi + (size_t)r0 * KCP2 + k0 + 2 * t;
                ahi[mt][0] = *(const unsigned int*)(base);
                ahi[mt][1] = *(const unsigned int*)(base + 8 * KCP2);
                ahi[mt][2] = *(const unsigned int*)(base + 8);
                ahi[mt][3] = *(const unsigned int*)(base + 8 * KCP2 + 8);
                const unsigned short* basel = sAlo + (size_t)r0 * KCP2 + k0 + 2 * t;
                alo[mt][0] = *(const unsigned int*)(basel);
                alo[mt][1] = *(const unsigned int*)(basel + 8 * KCP2);
                alo[mt][2] = *(const unsigned int*)(basel + 8);
                alo[mt][3] = *(const unsigned int*)(basel + 8 * KCP2 + 8);
            }
            unsigned int bhi[4][2], blo[4][2];
#pragma unroll
            for (int nt = 0; nt < 4; nt++) {
                int n0 = warpN * 32 + nt * 8 + g;
                const unsigned short* base = sBhi + (size_t)n0 * KCP2 + k0 + 2 * t;
                bhi[nt][0] = *(const unsigned int*)(base);
                bhi[nt][1] = *(const unsigned int*)(base + 8);
                const unsigned short* basel = sBlo + (size_t)n0 * KCP2 + k0 + 2 * t;
                blo[nt][0] = *(const unsigned int*)(basel);
                blo[nt][1] = *(const unsigned int*)(basel + 8);
            }
#pragma unroll
            for (int mt = 0; mt < 4; mt++)
#pragma unroll
                for (int nt = 0; nt < 4; nt++) {
                    mma_bf16(acc[mt][nt], ahi[mt], bhi[nt]);
                    mma_bf16(acc[mt][nt], ahi[mt], blo[nt]);
                    mma_bf16(acc[mt][nt], alo[mt], bhi[nt]);
                }
        }
    };

    // ---- phase 1: hidden = lrelu(src@W1 + b1) ----
    mma_phase();
    __syncthreads();   // all reads of sA/sB done

    // stage B = W2t hi/lo (overlaps with epilogue below)
    {
        unsigned int bb = sbase + (unsigned)(2 * TILE2) * 2;
#pragma unroll
        for (int i = 0; i < 16; i++) {
            int flat = i * 256 + tid;
            int tile = flat >> 11;
            int idx = flat & 2047;
            int row = idx >> 4;
            int seg = idx & 15;
            unsigned int daddr = bb + (unsigned)(tile * TILE2 + row * KCP2 + seg * 8) * 2;
            const unsigned short* p = ((tile == 0) ? g_w2t_hi : g_w2t_lo)
                                      + (size_t)row * 128 + seg * 8;
            cp16(daddr, p, 16);
        }
        asm volatile("cp.async.commit_group;" ::: "memory");
    }

    // epilogue 1: lrelu(acc + b1) -> split -> hidden into sA region
#pragma unroll
    for (int nt = 0; nt < 4; nt++) {
        int n0 = warpN * 32 + nt * 8 + t * 2;
        float c0 = b1v[n0], c1 = b1v[n0 + 1];
#pragma unroll
        for (int mt = 0; mt < 4; mt++) {
            int r0 = warpM * 64 + mt * 16 + g;
            float x0 = acc[mt][nt][0] + c0; x0 = x0 > 0.f ? x0 : 0.1f * x0;
            float x1 = acc[mt][nt][1] + c1; x1 = x1 > 0.f ? x1 : 0.1f * x1;
            unsigned int uh, ul;
            split2(x0, x1, uh, ul);
            *(unsigned int*)(sA + (size_t)r0 * KCP2 + n0) = uh;
            *(unsigned int*)(sA + TILE2 + (size_t)r0 * KCP2 + n0) = ul;
            int r1 = r0 + 8;
            float y0 = acc[mt][nt][2] + c0; y0 = y0 > 0.f ? y0 : 0.1f * y0;
            float y1 = acc[mt][nt][3] + c1; y1 = y1 > 0.f ? y1 : 0.1f * y1;
            split2(y0, y1, uh, ul);
            *(unsigned int*)(sA + (size_t)r1 * KCP2 + n0) = uh;
            *(unsigned int*)(sA + TILE2 + (size_t)r1 * KCP2 + n0) = ul;
            acc[mt][nt][0] = 0.f; acc[mt][nt][1] = 0.f;
            acc[mt][nt][2] = 0.f; acc[mt][nt][3] = 0.f;
        }
    }
    asm volatile("cp.async.wait_group 0;" ::: "memory");
    __syncthreads();

    // ---- phase 2: h = src + hidden@W2 + b2 ----
    mma_phase();

    // epilogue 2: add bias + residual, write g_h fp32
#pragma unroll
    for (int nt = 0; nt < 4; nt++) {
        int n0 = warpN * 32 + nt * 8 + t * 2;
        float c0 = b2v[n0], c1 = b2v[n0 + 1];
#pragma unroll
        for (int mt = 0; mt < 4; mt++) {
            int r0 = block_row + warpM * 64 + mt * 16 + g;
            if (r0 < M) {
                float2 sv = *(const float2*)(src + (size_t)r0 * 128 + n0);
                float2 o;
                o.x = acc[mt][nt][0] + c0 + sv.x;
                o.y = acc[mt][nt][1] + c1 + sv.y;
                *(float2*)(g_h + (size_t)r0 * 128 + n0) = o;
            }
            int r1 = r0 + 8;
            if (r1 < M) {
                float2 sv = *(const float2*)(src + (size_t)r1 * 128 + n0);
                float2 o;
                o.x = acc[mt][nt][2] + c0 + sv.x;
                o.y = acc[mt][nt][3] + c1 + sv.y;
                *(float2*)(g_h + (size_t)r1 * 128 + n0) = o;
            }
        }
    }
}

// ---------------- mma.sync readout GEMM, cp.async double-buffered ----------------
#define G2_NT 256
#define KC 64
#define KCP 72
#define TILE_HALFS (128 * KCP)
#define BUF_HALFS (4 * TILE_HALFS)
#define G2_SMEM (2 * BUF_HALFS * 2)

__global__ __launch_bounds__(G2_NT, 1) void gemm2_mma_kernel(
    const float* __restrict__ br, const float* __restrict__ dst_feat,
    float* __restrict__ out, int M)
{
    extern __shared__ __align__(16) unsigned short sh[];
    unsigned int sbase = smem_u32(sh);

    int tid = threadIdx.x;
    int wid = tid >> 5, lane = tid & 31;
    int g = lane >> 2, t = lane & 3;
    int warpM = wid & 1, warpN = wid >> 1;
    int block_row = blockIdx.x * 128;

    float acc[4][4][4];
#pragma unroll
    for (int mt = 0; mt < 4; mt++)
#pragma unroll
        for (int nt = 0; nt < 4; nt++)
#pragma unroll
            for (int q = 0; q < 4; q++) acc[mt][nt][q] = 0.f;

    auto stage = [&](int c, int buf) {
        unsigned int bb = sbase + (unsigned)buf * (BUF_HALFS * 2);
#pragma unroll
        for (int i = 0; i < 16; i++) {
            int flat = i * G2_NT + tid;
            int tile = flat >> 10;
            int idx = flat & 1023;
            int row = idx >> 3;
            int seg = idx & 7;
            unsigned int daddr = bb + (unsigned)(tile * TILE_HALFS + row * KCP + seg * 8) * 2;
            const unsigned short* src;
            int sz = 16;
            if (tile < 2) {
                int gr = block_row + row;
                const unsigned short* base = (tile == 0) ? g_agg_hi : g_agg_lo;
                src = base + (size_t)min(gr, MAX_DST - 1) * 512 + c * KC + seg * 8;
                if (gr >= M) sz = 0;
            } else {
                const unsigned short* base = (tile == 2) ? g_wt_hi : g_wt_lo;
                src = base + (size_t)row * 512 + c * KC + seg * 8;
            }
            cp16(daddr, src, sz);
        }
        asm volatile("cp.async.commit_group;" ::: "memory");
    };

    stage(0, 0);

    for (int c = 0; c < 8; c++) {
        int buf = c & 1;
        if (c < 7) stage(c + 1, (c + 1) & 1);
        if (c < 7)
            asm volatile("cp.async.wait_group 1;" ::: "memory");
        else
            asm volatile("cp.async.wait_group 0;" ::: "memory");
        __syncthreads();

        const unsigned short* sAhi = sh + (size_t)buf * BUF_HALFS;
        const unsigned short* sAlo = sAhi + TILE_HALFS;
        const unsigned short* sBhi = sAlo + TILE_HALFS;
        const unsigned short* sBlo = sBhi + TILE_HALFS;

#pragma unroll
        for (int ks = 0; ks < 4; ks++) {
            int k0 = ks * 16;
            unsigned int ahi[4][4], alo[4][4];
#pragma unroll
            for (int mt = 0; mt < 4; mt++) {
                int r0 = warpM * 64 + mt * 16 + g;
                const unsigned short* base = sAhi + (size_t)r0 * KCP + k0 + 2 * t;
                ahi[mt][0] = *(const unsigned int*)(base);
                ahi[mt][1] = *(const unsigned int*)(base + 8 * KCP);
                ahi[mt][2] = *(const unsigned int*)(base + 8);
                ahi[mt][3] = *(const unsigned int*)(base + 8 * KCP + 8);
                const unsigned short* basel = sAlo + (size_t)r0 * KCP + k0 + 2 * t;
                alo[mt][0] = *(const unsigned int*)(basel);
                alo[mt][1] = *(const unsigned int*)(basel + 8 * KCP);
                alo[mt][2] = *(const unsigned int*)(basel + 8);
                alo[mt][3] = *(const unsigned int*)(basel + 8 * KCP + 8);
            }
            unsigned int bhi[4][2], blo[4][2];
#pragma unroll
            for (int nt = 0; nt < 4; nt++) {
                int n0 = warpN * 32 + nt * 8 + g;
                const unsigned short* base = sBhi + (size_t)n0 * KCP + k0 + 2 * t;
                bhi[nt][0] = *(const unsigned int*)(base);
                bhi[nt][1] = *(const unsigned int*)(base + 8);
                const unsigned short* basel = sBlo + (size_t)n0 * KCP + k0 + 2 * t;
                blo[nt][0] = *(const unsigned int*)(basel);
                blo[nt][1] = *(const unsigned int*)(basel + 8);
            }
#pragma unroll
            for (int mt = 0; mt < 4; mt++)
#pragma unroll
                for (int nt = 0; nt < 4; nt++) {
                    mma_bf16(acc[mt][nt], ahi[mt], bhi[nt]);
                    mma_bf16(acc[mt][nt], ahi[mt], blo[nt]);
                    mma_bf16(acc[mt][nt], alo[mt], bhi[nt]);
                }
        }
        __syncthreads();
    }

#pragma unroll
    for (int nt = 0; nt < 4; nt++) {
        int n0 = warpN * 32 + nt * 8 + t * 2;
        float b0 = br[n0], b1 = br[n0 + 1];
#pragma unroll
        for (int mt = 0; mt < 4; mt++) {
            int r0 = block_row + warpM * 64 + mt * 16 + g;
            if (r0 < M) {
                float2 dd = *(const float2*)(dst_feat + (size_t)r0 * 128 + n0);
                float x0 = acc[mt][nt][0] + b0; x0 = x0 > 0.f ? x0 : 0.1f * x0;
                float x1 = acc[mt][nt][1] + b1; x1 = x1 > 0.f ? x1 : 0.1f * x1;
                float2 o; o.x = x0 + dd.x; o.y = x1 + dd.y;
                *(float2*)(out + (size_t)r0 * 128 + n0) = o;
            }
            int r1 = r0 + 8;
            if (r1 < M) {
                float2 dd = *(const float2*)(dst_feat + (size_t)r1 * 128 + n0);
                float x0 = acc[mt][nt][2] + b0; x0 = x0 > 0.f ? x0 : 0.1f * x0;
                float x1 = acc[mt][nt][3] + b1; x1 = x1 > 0.f ? x1 : 0.1f * x1;
                float2 o; o.x = x0 + dd.x; o.y = x1 + dd.y;
                *(float2*)(out + (size_t)r1 * 128 + n0) = o;
            }
        }
    }
}

// ---------------- launch ----------------
extern "C" void kernel_launch(void* const* d_in, const int* in_sizes, int n_in,
                              void* d_out, int out_size) {
    const float* src_feat = (const float*)d_in[0];
    const float* dst_feat = (const float*)d_in[1];
    const int*   edge_src = (const int*)d_in[2];
    const int*   edge_dst = (const int*)d_in[3];
    const float* W1 = (const float*)d_in[4];
    const float* b1 = (const float*)d_in[5];
    const float* W2 = (const float*)d_in[6];
    const float* b2 = (const float*)d_in[7];
    const float* Wr = (const float*)d_in[8];
    const float* br = (const float*)d_in[9];
    float* out = (float*)d_out;

    int n_src = in_sizes[0] / H;
    int n_dst = in_sizes[1] / H;
    int E     = in_sizes[2];

    int gm_src = (n_src + 127) / 128;   // 157
    int gm_tc  = (n_dst + 127) / 128;   // 157

    static cudaStream_t side = nullptr, side2 = nullptr;
    static cudaEvent_t ev_fork = nullptr, ev_join = nullptr, ev_join2 = nullptr;
    if (!side) {
        cudaStreamCreateWithFlags(&side, cudaStreamNonBlocking);
        cudaStreamCreateWithFlags(&side2, cudaStreamNonBlocking);
        cudaEventCreateWithFlags(&ev_fork, cudaEventDisableTiming);
        cudaEventCreateWithFlags(&ev_join, cudaEventDisableTiming);
        cudaEventCreateWithFlags(&ev_join2, cudaEventDisableTiming);
        cudaFuncSetAttribute(mlp_mma_kernel,
                             cudaFuncAttributeMaxDynamicSharedMemorySize,
                             MLP_SMEM);
        cudaFuncSetAttribute(gemm2_mma_kernel,
                             cudaFuncAttributeMaxDynamicSharedMemorySize,
                             G2_SMEM);
    }

    cudaEventRecord(ev_fork, 0);
    cudaStreamWaitEvent(side, ev_fork, 0);
    cudaStreamWaitEvent(side2, ev_fork, 0);

    // side: CSR build — count(+rank), one scan, atomic-free scatter
    count_kernel<<<(E + 1023) / 1024, 256, 0, side>>>(edge_dst, E);
    scan_full_kernel<<<1, 1024, 0, side>>>(n_dst);
    scatter_kernel<<<(E + 1023) / 1024, 256, 0, side>>>(edge_src, edge_dst, E);
    cudaEventRecord(ev_join, side);

    // side2: weight transpose/split (gates MLP and gemm2)
    w_prep_kernel<<<48, 256, 0, side2>>>(Wr, W1, W2);
    cudaEventRecord(ev_join2, side2);

    // main: tensor-core fused MLP (needs W1t/W2t)
    cudaStreamWaitEvent(0, ev_join2, 0);
    mlp_mma_kernel<<<gm_src, 256, MLP_SMEM>>>(src_feat, b1, b2, n_src);

    // join CSR, then aggregation
    cudaStreamWaitEvent(0, ev_join, 0);
    agg_kernel<<<(n_dst * 32 + 255) / 256, 256>>>(dst_feat, n_dst);

    // readout GEMM
    gemm2_mma_kernel<<<gm_tc, G2_NT, G2_SMEM>>>(br, dst_feat, out, n_dst);
}